// round 1
// baseline (speedup 1.0000x reference)
#include <cuda_runtime.h>
#include <math.h>
#include <stdint.h>

typedef unsigned long long ull;

#define SEQ   1024
#define BATCH 64
#define DH    256
#define DIN   256
#define GCOLS 1024   // 4 gates * DH

// ---------------- device scratch (static allocs only; no cudaMalloc) --------
__device__ float g_xq[SEQ * GCOLS * BATCH / 1];   // 1024*1024*64 = 67,108,864 floats (256MB)
__device__ float g_h[DH * BATCH];                  // h state, layout [k][b]
__device__ volatile unsigned g_gen;                // barrier generation (monotonic)
__device__ unsigned g_cnt;                         // barrier arrival count (returns to 0)

// ---------------- f32x2 packed-FMA helpers (Blackwell) ----------------------
__device__ __forceinline__ ull fma2(ull a, ull b, ull c) {
    ull d;
    asm("fma.rn.f32x2 %0, %1, %2, %3;" : "=l"(d) : "l"(a), "l"(b), "l"(c));
    return d;
}
__device__ __forceinline__ ull pack2(float x, float y) {
    ull r;
    asm("mov.b64 %0, {%1, %2};" : "=l"(r) : "f"(x), "f"(y));
    return r;
}
__device__ __forceinline__ float2 unpack2(ull v) {
    float2 r;
    asm("mov.b64 {%0, %1}, %2;" : "=f"(r.x), "=f"(r.y) : "l"(v));
    return r;
}

// ======================= Phase 1: X projection GEMM =========================
// C[t, c, b] = sum_k X[t,b,k] * W_g[k, j] + bias_g[j],  c = g*256 + j
// Block: BM=64 rows (= one t, all 64 batches), BN=64 cols (one gate slice), K=256.
__global__ __launch_bounds__(256) void xproj_kernel(
    const float* __restrict__ X,
    const float* __restrict__ Wf, const float* __restrict__ Wi,
    const float* __restrict__ Wg, const float* __restrict__ Wo,
    const float* __restrict__ bf, const float* __restrict__ bi,
    const float* __restrict__ bg, const float* __restrict__ bo)
{
    __shared__ float As[16 * 68];   // [k][row], padded
    __shared__ float Bs[16 * 68];   // [k][col], padded

    const int t    = blockIdx.y;
    const int bx   = blockIdx.x;           // 0..15
    const int gsel = bx >> 2;              // gate: 0=f 1=i 2=g 3=o
    const int j0   = (bx & 3) * 64;        // column offset within gate
    const float* W    = (gsel == 0) ? Wf : (gsel == 1) ? Wi : (gsel == 2) ? Wg : Wo;
    const float* bias = (gsel == 0) ? bf : (gsel == 1) ? bi : (gsel == 2) ? bg : bo;

    const int tx    = threadIdx.x;
    const int trow4 = (tx >> 4) * 4;       // 0..60 (batch rows)
    const int tcol4 = (tx & 15) * 4;       // 0..60 (cols)

    // loader indices
    const int arow = tx >> 2;              // 0..63
    const int akq  = (tx & 3) * 4;         // k offset 0,4,8,12
    const int bk   = tx >> 4;              // 0..15
    const int bc4  = (tx & 15) * 4;

    const float* Aptr = X + ((size_t)t * 64 + arow) * 256 + akq;
    const float* Bptr = W + (size_t)bk * 256 + j0 + bc4;

    ull acc[8];                             // acc[2*jj + half], half0 = rows 0,1; half1 = rows 2,3
    #pragma unroll
    for (int i = 0; i < 8; ++i) acc[i] = 0ull;

    float4 aReg = *(const float4*)Aptr;
    float4 bReg = *(const float4*)Bptr;

    for (int kt = 0; kt < 16; ++kt) {
        __syncthreads();   // previous inner done
        As[(akq + 0) * 68 + arow] = aReg.x;
        As[(akq + 1) * 68 + arow] = aReg.y;
        As[(akq + 2) * 68 + arow] = aReg.z;
        As[(akq + 3) * 68 + arow] = aReg.w;
        *(float4*)&Bs[bk * 68 + bc4] = bReg;
        if (kt < 15) {
            aReg = *(const float4*)(Aptr + (kt + 1) * 16);
            bReg = *(const float4*)(Bptr + (size_t)(kt + 1) * 16 * 256);
        }
        __syncthreads();

        #pragma unroll
        for (int k = 0; k < 16; ++k) {
            float4 a4 = *(const float4*)&As[k * 68 + trow4];
            float4 b4 = *(const float4*)&Bs[k * 68 + tcol4];
            ull a01 = pack2(a4.x, a4.y);
            ull a23 = pack2(a4.z, a4.w);
            ull bb;
            bb = pack2(b4.x, b4.x); acc[0] = fma2(a01, bb, acc[0]); acc[1] = fma2(a23, bb, acc[1]);
            bb = pack2(b4.y, b4.y); acc[2] = fma2(a01, bb, acc[2]); acc[3] = fma2(a23, bb, acc[3]);
            bb = pack2(b4.z, b4.z); acc[4] = fma2(a01, bb, acc[4]); acc[5] = fma2(a23, bb, acc[5]);
            bb = pack2(b4.w, b4.w); acc[6] = fma2(a01, bb, acc[6]); acc[7] = fma2(a23, bb, acc[7]);
        }
    }

    // epilogue: add bias, store transposed C[t][c][b]
    #pragma unroll
    for (int jj = 0; jj < 4; ++jj) {
        float bv = bias[j0 + tcol4 + jj];
        float2 p01 = unpack2(acc[2 * jj]);
        float2 p23 = unpack2(acc[2 * jj + 1]);
        float4 outv = make_float4(p01.x + bv, p01.y + bv, p23.x + bv, p23.y + bv);
        size_t c = (size_t)bx * 64 + tcol4 + jj;
        *(float4*)&g_xq[(size_t)t * 65536 + c * 64 + trow4] = outv;
    }
}

// ======================= Phase 2: persistent recurrence =====================
#define NBLK 128
#define NTHR 128

__device__ __forceinline__ void grid_barrier() {
    __syncthreads();
    if (threadIdx.x == 0) {
        unsigned old = g_gen;
        __threadfence();
        if (atomicAdd(&g_cnt, 1u) == NBLK - 1u) {
            atomicExch(&g_cnt, 0u);
            __threadfence();
            g_gen = old + 1u;
        } else {
            while (g_gen == old) { }
        }
        __threadfence();
    }
    __syncthreads();
}

// 128 CTAs, each owns 2 hidden units (8 gate-cols). 128 threads, 4 outputs each
// (4 batches x 1 gate-col). Wh duplicated into f32-pairs in smem for FFMA2.
__global__ __launch_bounds__(NTHR, 1) void lstm_seq_kernel(
    const float* __restrict__ Wf, const float* __restrict__ Wi,
    const float* __restrict__ Wg, const float* __restrict__ Wo,
    float* __restrict__ out)
{
    extern __shared__ float sm[];
    float* h_sh    = sm;                       // 256*64   = 16384 floats, [k][b]
    float* wh2     = sm + 16384;               // 256*8*2  = 4096 floats, dup pairs [k][lc][2]
    float* gate_sh = sm + 16384 + 4096;        // 8*72     = 576 floats
    float* c_sh    = gate_sh + 576;            // 2*64     = 128 floats

    const int tx   = threadIdx.x;
    const int u0   = blockIdx.x * 2;           // first hidden unit owned
    const int lc   = tx & 7;                   // local gate-col: g*2 + uu
    const int b0   = (tx >> 3) * 4;            // 4 batches per thread
    const int gsel = lc >> 1;
    const int uu   = lc & 1;
    const int cglob = gsel * 256 + u0 + uu;

    // ---- load Wh slice (rows 256..511 of W), duplicated as pairs ----
    for (int idx = tx; idx < 2048; idx += NTHR) {
        int k  = idx >> 3;
        int l  = idx & 7;
        int g2 = l >> 1;
        int j  = u0 + (l & 1);
        const float* W = (g2 == 0) ? Wf : (g2 == 1) ? Wi : (g2 == 2) ? Wg : Wo;
        float w = W[(size_t)(256 + k) * 256 + j];
        wh2[2 * idx]     = w;
        wh2[2 * idx + 1] = w;
    }

    // ---- init state ----
    {
        int b = tx & 63, u = tx >> 6;
        g_h[(u0 + u) * 64 + b] = 0.0f;
        c_sh[u * 64 + b] = 0.0f;
    }
    __threadfence();
    grid_barrier();

    float* outs = out;
    float* hx   = out + (size_t)SEQ * BATCH * DH;
    float* cxo  = hx + BATCH * DH;

    const ull* wp = (const ull*)wh2 + lc;      // wp[k*8] = dup pair for (k, lc)

    for (int t = 0; t < SEQ; ++t) {
        // issue Xproj load early (consumed as acc init)
        ulonglong2 xq = *(const ulonglong2*)&g_xq[(size_t)t * 65536 + (size_t)cglob * 64 + b0];

        // broadcast h into smem (64KB from L2)
        #pragma unroll
        for (int i = 0; i < 32; ++i) {
            int idx = tx + i * NTHR;
            *(float4*)&h_sh[idx * 4] = *(const float4*)&g_h[idx * 4];
        }
        __syncthreads();

        // ---- recurrent GEMM: acc(b, lc) += sum_k h[k][b] * Wh[k][lc] ----
        ull acc0 = xq.x;   // batches b0, b0+1
        ull acc1 = xq.y;   // batches b0+2, b0+3
        const float* hp = h_sh + b0;
        #pragma unroll 8
        for (int k = 0; k < 256; ++k) {
            ulonglong2 hh = *(const ulonglong2*)(hp + (k << 6));
            ull ww = wp[k << 3];
            acc0 = fma2(hh.x, ww, acc0);
            acc1 = fma2(hh.y, ww, acc1);
        }

        // ---- activations ----
        float2 v01 = unpack2(acc0);
        float2 v23 = unpack2(acc1);
        float4 a;
        if (gsel == 2) {
            a.x = tanhf(v01.x); a.y = tanhf(v01.y);
            a.z = tanhf(v23.x); a.w = tanhf(v23.y);
        } else {
            a.x = 1.0f / (1.0f + __expf(-v01.x));
            a.y = 1.0f / (1.0f + __expf(-v01.y));
            a.z = 1.0f / (1.0f + __expf(-v23.x));
            a.w = 1.0f / (1.0f + __expf(-v23.y));
        }
        *(float4*)&gate_sh[lc * 72 + b0] = a;
        __syncthreads();

        // ---- state update: one thread per (batch, unit) ----
        {
            int b = tx & 63, u = tx >> 6;
            float f  = gate_sh[(0 + u) * 72 + b];
            float ii = gate_sh[(2 + u) * 72 + b];
            float gg = gate_sh[(4 + u) * 72 + b];
            float oo = gate_sh[(6 + u) * 72 + b];
            float c  = f * c_sh[u * 64 + b] + ii * gg;
            c_sh[u * 64 + b] = c;
            float h = oo * tanhf(c);
            int j = u0 + u;
            g_h[j * 64 + b] = h;
            outs[((size_t)t * 64 + b) * 256 + j] = h;
            if (t == SEQ - 1) {
                hx[b * 256 + j]  = h;
                cxo[b * 256 + j] = c;
            }
        }
        grid_barrier();
    }
}

// ============================== launch ======================================
extern "C" void kernel_launch(void* const* d_in, const int* in_sizes, int n_in,
                              void* d_out, int out_size)
{
    (void)in_sizes; (void)n_in; (void)out_size;
    const float* X  = (const float*)d_in[0];
    const float* Wf = (const float*)d_in[1];
    const float* bf = (const float*)d_in[2];
    const float* Wi = (const float*)d_in[3];
    const float* bi = (const float*)d_in[4];
    const float* Wg = (const float*)d_in[5];
    const float* bg = (const float*)d_in[6];
    const float* Wo = (const float*)d_in[7];
    const float* bo = (const float*)d_in[8];
    float* out = (float*)d_out;

    dim3 g1(16, 1024);
    xproj_kernel<<<g1, 256>>>(X, Wf, Wi, Wg, Wo, bf, bi, bg, bo);

    const int smem2 = (16384 + 4096 + 576 + 128) * 4;   // 84,736 B
    cudaFuncSetAttribute(lstm_seq_kernel,
                         cudaFuncAttributeMaxDynamicSharedMemorySize, smem2);
    lstm_seq_kernel<<<NBLK, NTHR, smem2>>>(Wf, Wi, Wg, Wo, out);
}

// round 4
// speedup vs baseline: 1.9660x; 1.9660x over previous
#include <cuda_runtime.h>
#include <math.h>
#include <stdint.h>

typedef unsigned long long ull;

#define SEQ   1024
#define BATCH 64
#define DH    256
#define DIN   256
#define NBLK  128
#define NTHR  256

// ---------------- device scratch (static allocs only) -----------------------
__device__ float    g_xq[(size_t)SEQ * 1024 * 64];   // [t][gatecol][b], 256MB
__device__ float    g_hbuf[2][DH * BATCH];           // double-buffered h, [unit][batch]
__device__ unsigned g_flag4[SEQ + 1][4];             // per-step, per-quarter producer flags

// ---------------- f32x2 packed helpers (Blackwell) --------------------------
__device__ __forceinline__ ull fma2(ull a, ull b, ull c) {
    ull d;
    asm("fma.rn.f32x2 %0, %1, %2, %3;" : "=l"(d) : "l"(a), "l"(b), "l"(c));
    return d;
}
__device__ __forceinline__ ull add2(ull a, ull b) {
    ull d;
    asm("add.rn.f32x2 %0, %1, %2;" : "=l"(d) : "l"(a), "l"(b));
    return d;
}
__device__ __forceinline__ ull pack2(float x, float y) {
    ull r;
    asm("mov.b64 %0, {%1, %2};" : "=l"(r) : "f"(x), "f"(y));
    return r;
}
__device__ __forceinline__ float2 unpack2(ull v) {
    float2 r;
    asm("mov.b64 {%0, %1}, %2;" : "=f"(r.x), "=f"(r.y) : "l"(v));
    return r;
}
__device__ __forceinline__ ulonglong2 ldcg_u2(const void* p) {
    ulonglong2 v;
    asm volatile("ld.global.cg.v2.u64 {%0, %1}, [%2];"
                 : "=l"(v.x), "=l"(v.y) : "l"(p));
    return v;
}
__device__ __forceinline__ unsigned ld_acq(const unsigned* p) {
    unsigned v;
    asm volatile("ld.acquire.gpu.global.u32 %0, [%1];" : "=r"(v) : "l"(p));
    return v;
}
__device__ __forceinline__ void red_rel(unsigned* p) {
    unsigned one = 1u;
    asm volatile("red.release.gpu.global.add.u32 [%0], %1;" :: "l"(p), "r"(one) : "memory");
}

// ======================= Phase 1: X projection GEMM =========================
// g_xq[t, c, b] = sum_k X[t,b,k] * W_g[k, j] + bias_g[j],  c = g*256 + j
__global__ __launch_bounds__(256) void xproj_kernel(
    const float* __restrict__ X,
    const float* __restrict__ Wf, const float* __restrict__ Wi,
    const float* __restrict__ Wg, const float* __restrict__ Wo,
    const float* __restrict__ bf, const float* __restrict__ bi,
    const float* __restrict__ bg, const float* __restrict__ bo)
{
    __shared__ float As[16 * 68];   // [k][row]
    __shared__ float Bs[16 * 68];   // [k][col]

    const int t    = blockIdx.y;
    const int bx   = blockIdx.x;           // 0..15
    const int gsel = bx >> 2;
    const int j0   = (bx & 3) * 64;
    const float* W    = (gsel == 0) ? Wf : (gsel == 1) ? Wi : (gsel == 2) ? Wg : Wo;
    const float* bias = (gsel == 0) ? bf : (gsel == 1) ? bi : (gsel == 2) ? bg : bo;

    const int tx = threadIdx.x;

    // zero next-launch flags (re-zeroed every replay for determinism)
    if (bx == 0 && tx < 4) g_flag4[t][tx] = 0u;
    if (bx == 0 && t == 0 && tx >= 4 && tx < 8) g_flag4[SEQ][tx - 4] = 0u;

    const int trow4 = (tx >> 4) * 4;
    const int tcol4 = (tx & 15) * 4;

    const int arow = tx >> 2;
    const int akq  = (tx & 3) * 4;
    const int bk   = tx >> 4;
    const int bc4  = (tx & 15) * 4;

    const float* Aptr = X + ((size_t)t * 64 + arow) * 256 + akq;
    const float* Bptr = W + (size_t)bk * 256 + j0 + bc4;

    ull acc[8];
    #pragma unroll
    for (int i = 0; i < 8; ++i) acc[i] = 0ull;

    float4 aReg = *(const float4*)Aptr;
    float4 bReg = *(const float4*)Bptr;

    for (int kt = 0; kt < 16; ++kt) {
        __syncthreads();
        As[(akq + 0) * 68 + arow] = aReg.x;
        As[(akq + 1) * 68 + arow] = aReg.y;
        As[(akq + 2) * 68 + arow] = aReg.z;
        As[(akq + 3) * 68 + arow] = aReg.w;
        *(float4*)&Bs[bk * 68 + bc4] = bReg;
        if (kt < 15) {
            aReg = *(const float4*)(Aptr + (kt + 1) * 16);
            bReg = *(const float4*)(Bptr + (size_t)(kt + 1) * 16 * 256);
        }
        __syncthreads();

        #pragma unroll
        for (int k = 0; k < 16; ++k) {
            float4 a4 = *(const float4*)&As[k * 68 + trow4];
            float4 b4 = *(const float4*)&Bs[k * 68 + tcol4];
            ull a01 = pack2(a4.x, a4.y);
            ull a23 = pack2(a4.z, a4.w);
            ull bb;
            bb = pack2(b4.x, b4.x); acc[0] = fma2(a01, bb, acc[0]); acc[1] = fma2(a23, bb, acc[1]);
            bb = pack2(b4.y, b4.y); acc[2] = fma2(a01, bb, acc[2]); acc[3] = fma2(a23, bb, acc[3]);
            bb = pack2(b4.z, b4.z); acc[4] = fma2(a01, bb, acc[4]); acc[5] = fma2(a23, bb, acc[5]);
            bb = pack2(b4.w, b4.w); acc[6] = fma2(a01, bb, acc[6]); acc[7] = fma2(a23, bb, acc[7]);
        }
    }

    #pragma unroll
    for (int jj = 0; jj < 4; ++jj) {
        float bv = bias[j0 + tcol4 + jj];
        float2 p01 = unpack2(acc[2 * jj]);
        float2 p23 = unpack2(acc[2 * jj + 1]);
        float4 outv = make_float4(p01.x + bv, p01.y + bv, p23.x + bv, p23.y + bv);
        size_t c = (size_t)bx * 64 + tcol4 + jj;
        *(float4*)&g_xq[(size_t)t * 65536 + c * 64 + trow4] = outv;
    }
}

// ======================= Phase 2: persistent recurrence =====================
// 128 CTAs x 256 thr. CTA owns 2 hidden units (8 gate-cols). K-split GEMM:
// thread = (bg 0..15: 4 batches) x (kc 0..15: 16 k). h read once per CTA via
// LDG.cg (no smem staging). Double-buffered h + forward flags (no barrier).
__global__ __launch_bounds__(NTHR, 1) void lstm_seq_kernel(
    const float* __restrict__ Wf, const float* __restrict__ Wi,
    const float* __restrict__ Wg, const float* __restrict__ Wo,
    float* __restrict__ out)
{
    extern __shared__ char smx[];
    ull* wh2    = (ull*)smx;          // [k][8 cols] dup pairs : 2048 ull (16KB)
    ull* pp     = wh2 + 2048;         // [16 kc][256]          : 4096 ull (32KB)
    ull* gate_s = pp + 4096;          // [8 cols][32 bpairs]   : 256 ull  (2KB)
    ull* c_s    = gate_s + 256;       // [2 units][32 bpairs]  : 64 ull

    const int tx = threadIdx.x;
    const int bx = blockIdx.x;
    const int u0 = bx << 1;            // first hidden unit owned
    const int bg = tx & 15;            // batch group (4 batches)
    const int kc = tx >> 4;            // k-chunk (16 k)

    // ---- load Wh slice, duplicated pairs: wh2[k*8 + c], c = g*2 + uu ----
    for (int idx = tx; idx < 2048; idx += NTHR) {
        int k = idx >> 3, c = idx & 7;
        const float* W = (c < 4) ? ((c < 2) ? Wf : Wi) : ((c < 6) ? Wg : Wo);
        float w = W[(size_t)(256 + k) * 256 + u0 + (c & 1)];
        wh2[idx] = pack2(w, w);
    }

    // ---- init h(0)=0, c=0, signal flag[0] ----
    if (tx < 64) {
        c_s[tx] = 0ull;
        int u = tx >> 5, bp = tx & 31;
        *(ull*)&g_hbuf[0][(u0 + u) * 64 + (bp << 1)] = 0ull;
    }
    __syncthreads();
    if (tx == 0) red_rel(&g_flag4[0][bx >> 5]);

    // reduce-role constants (thread tx -> col rc, batch-pair rbp)
    const int rc  = tx >> 5;
    const int rbp = tx & 31;
    const int rg  = rc >> 1;
    const size_t xq_off = (size_t)(rg * 256 + u0 + (rc & 1)) * 64 + (rbp << 1);

    float* outs = out;
    float* hxo  = out + (size_t)SEQ * 64 * 256;
    float* cxo  = hxo + 64 * 256;

    const ull* wpp = wh2 + kc * 128;          // w dup pairs for my k-chunk
    const int  hoff = kc * 16 * 64 + (bg << 2);

    for (int t = 0; t < SEQ; ++t) {
        // prefetch x-projection (independent of flags)
        ull xq = *(const ull*)&g_xq[(size_t)t * 65536 + xq_off];

        // wait for all producers of h(t): 4 lanes poll 4 quarter-flags
        if (tx >= 252) {
            const unsigned* fp = &g_flag4[t][tx - 252];
            while (ld_acq(fp) != 32u) { }
        }
        __syncthreads();

        // ---- K-split GEMM: acc[2c+p] over 16 k, h via LDG.cg ----
        const float* hb = g_hbuf[t & 1] + hoff;
        ull acc[16];
        #pragma unroll
        for (int i = 0; i < 16; ++i) acc[i] = 0ull;
        #pragma unroll
        for (int k = 0; k < 16; ++k) {
            ulonglong2 hh = ldcg_u2(hb + (k << 6));
            const ulonglong2* wv = (const ulonglong2*)(wpp + (k << 3));
            ulonglong2 w01 = wv[0], w23 = wv[1], w45 = wv[2], w67 = wv[3];
            acc[0]  = fma2(hh.x, w01.x, acc[0]);  acc[1]  = fma2(hh.y, w01.x, acc[1]);
            acc[2]  = fma2(hh.x, w01.y, acc[2]);  acc[3]  = fma2(hh.y, w01.y, acc[3]);
            acc[4]  = fma2(hh.x, w23.x, acc[4]);  acc[5]  = fma2(hh.y, w23.x, acc[5]);
            acc[6]  = fma2(hh.x, w23.y, acc[6]);  acc[7]  = fma2(hh.y, w23.y, acc[7]);
            acc[8]  = fma2(hh.x, w45.x, acc[8]);  acc[9]  = fma2(hh.y, w45.x, acc[9]);
            acc[10] = fma2(hh.x, w45.y, acc[10]); acc[11] = fma2(hh.y, w45.y, acc[11]);
            acc[12] = fma2(hh.x, w67.x, acc[12]); acc[13] = fma2(hh.y, w67.x, acc[13]);
            acc[14] = fma2(hh.x, w67.y, acc[14]); acc[15] = fma2(hh.y, w67.y, acc[15]);
        }
        // store partials: pp[kc][c*32 + 2bg + p]
        {
            ull* pdst = pp + kc * 256 + (bg << 1);
            #pragma unroll
            for (int c = 0; c < 8; ++c) {
                pdst[(c << 5)    ] = acc[2 * c];
                pdst[(c << 5) + 1] = acc[2 * c + 1];
            }
        }
        __syncthreads();

        // ---- reduce 16 partials (tree, f32x2 adds), + xq, activation ----
        ull s0 = add2(pp[tx],        pp[tx + 256]);
        ull s1 = add2(pp[tx + 512],  pp[tx + 768]);
        ull s2 = add2(pp[tx + 1024], pp[tx + 1280]);
        ull s3 = add2(pp[tx + 1536], pp[tx + 1792]);
        ull s4 = add2(pp[tx + 2048], pp[tx + 2304]);
        ull s5 = add2(pp[tx + 2560], pp[tx + 2816]);
        ull s6 = add2(pp[tx + 3072], pp[tx + 3328]);
        ull s7 = add2(pp[tx + 3584], pp[tx + 3840]);
        s0 = add2(s0, s1); s2 = add2(s2, s3); s4 = add2(s4, s5); s6 = add2(s6, s7);
        s0 = add2(s0, s2); s4 = add2(s4, s6);
        ull s = add2(add2(s0, s4), xq);

        float2 v = unpack2(s);
        float2 a;
        if (rg == 2) {                         // g gate -> tanh
            a.x = tanhf(v.x); a.y = tanhf(v.y);
        } else {                               // f, i, o -> sigmoid
            a.x = 1.0f / (1.0f + __expf(-v.x));
            a.y = 1.0f / (1.0f + __expf(-v.y));
        }
        gate_s[tx] = pack2(a.x, a.y);
        __syncthreads();

        // ---- state update: 64 threads, each (unit u, batch-pair bp) ----
        if (tx < 64) {
            int u = tx >> 5, bp = tx & 31;
            float2 f  = unpack2(gate_s[(0 + u) * 32 + bp]);
            float2 ii = unpack2(gate_s[(2 + u) * 32 + bp]);
            float2 gg = unpack2(gate_s[(4 + u) * 32 + bp]);
            float2 oo = unpack2(gate_s[(6 + u) * 32 + bp]);
            float2 co = unpack2(c_s[tx]);
            float c0 = f.x * co.x + ii.x * gg.x;
            float c1 = f.y * co.y + ii.y * gg.y;
            c_s[tx] = pack2(c0, c1);
            float h0 = oo.x * tanhf(c0);
            float h1 = oo.y * tanhf(c1);
            int j = u0 + u;
            int b = bp << 1;
            *(ull*)&g_hbuf[(t + 1) & 1][j * 64 + b] = pack2(h0, h1);
            outs[((size_t)t * 64 + b) * 256 + j]     = h0;
            outs[((size_t)t * 64 + b + 1) * 256 + j] = h1;
            if (t == SEQ - 1) {
                hxo[b * 256 + j] = h0; hxo[(b + 1) * 256 + j] = h1;
                cxo[b * 256 + j] = c0; cxo[(b + 1) * 256 + j] = c1;
            }
        }
        __syncthreads();
        if (tx == 0) red_rel(&g_flag4[t + 1][bx >> 5]);
    }
}

// ============================== launch ======================================
extern "C" void kernel_launch(void* const* d_in, const int* in_sizes, int n_in,
                              void* d_out, int out_size)
{
    (void)in_sizes; (void)n_in; (void)out_size;
    const float* X  = (const float*)d_in[0];
    const float* Wf = (const float*)d_in[1];
    const float* bf = (const float*)d_in[2];
    const float* Wi = (const float*)d_in[3];
    const float* bi = (const float*)d_in[4];
    const float* Wg = (const float*)d_in[5];
    const float* bg = (const float*)d_in[6];
    const float* Wo = (const float*)d_in[7];
    const float* bo = (const float*)d_in[8];
    float* out = (float*)d_out;

    dim3 g1(16, 1024);
    xproj_kernel<<<g1, 256>>>(X, Wf, Wi, Wg, Wo, bf, bi, bg, bo);

    const int smem2 = 6464 * 8;   // 51,712 B
    cudaFuncSetAttribute(lstm_seq_kernel,
                         cudaFuncAttributeMaxDynamicSharedMemorySize, smem2);
    lstm_seq_kernel<<<NBLK, NTHR, smem2>>>(Wf, Wi, Wg, Wo, out);
}